// round 2
// baseline (speedup 1.0000x reference)
#include <cuda_runtime.h>
#include <cuda_bf16.h>

// Problem constants
#define BATCH   32768
#define CH      3
#define D       768          // 3*16*16 compressed features per sample
#define D4      192          // D/4

// Scratch for the folded weight vector (allocation-free rule: __device__ global)
__device__ float g_weff[D];

// ---------------------------------------------------------------------------
// Kernel 1: fold lhs/rhs/W into W_eff[768].
// One block per output element o = ch*256 + (r*8+p)*16 + (c*8+q).
// 256 threads, thread t = P*16 + Q; block-reduce the 256 terms.
// ---------------------------------------------------------------------------
__global__ void fold_weff_kernel(const float* __restrict__ lhs,   // [2,16,8]
                                 const float* __restrict__ rhs,   // [2,8,16]
                                 const float* __restrict__ W)     // [3072]
{
    const int o   = blockIdx.x;          // 0..767
    const int ch  = o >> 8;              // /256
    const int rem = o & 255;
    const int rr  = rem >> 4;            // compressed row 0..15
    const int cc  = rem & 15;            // compressed col 0..15
    const int r   = rr >> 3;             // row block
    const int p   = rr & 7;
    const int c   = cc >> 3;             // col block
    const int q   = cc & 7;

    const int t = threadIdx.x;           // 0..255
    const int P = t >> 4;                // 0..15
    const int Q = t & 15;                // 0..15

    // lhs[r, P, p], rhs[c, q, Q], W[ch, r*16+P, c*16+Q]
    float term = lhs[r * 128 + P * 8 + p]
               * rhs[c * 128 + q * 16 + Q]
               * W[ch * 1024 + (r * 16 + P) * 32 + (c * 16 + Q)];

    // block reduction: warp shfl then smem across the 8 warps
    #pragma unroll
    for (int off = 16; off > 0; off >>= 1)
        term += __shfl_xor_sync(0xFFFFFFFFu, term, off);

    __shared__ float warp_sums[8];
    const int lane = t & 31;
    const int wid  = t >> 5;
    if (lane == 0) warp_sums[wid] = term;
    __syncthreads();

    if (t == 0) {
        float s = 0.f;
        #pragma unroll
        for (int w = 0; w < 8; w++) s += warp_sums[w];
        g_weff[o] = s;
    }
}

// ---------------------------------------------------------------------------
// Kernel 2: out[n] = dot(x[n, :], W_eff) + b.  One warp per row.
// x rows are contiguous 768 floats; lanes read float4 -> fully coalesced.
// ---------------------------------------------------------------------------
__global__ __launch_bounds__(128)
void gemv_kernel(const float4* __restrict__ x,    // [BATCH * D4]
                 const float*  __restrict__ bptr, // [1]
                 float*        __restrict__ out)  // [BATCH]
{
    const int gwarp = (blockIdx.x * blockDim.x + threadIdx.x) >> 5;
    const int lane  = threadIdx.x & 31;
    if (gwarp >= BATCH) return;

    const float4* __restrict__ xr = x + (size_t)gwarp * D4;
    const float4* __restrict__ w4 = reinterpret_cast<const float4*>(g_weff);

    float acc = 0.f;
    #pragma unroll
    for (int k = 0; k < 6; k++) {
        float4 v = xr[lane + k * 32];
        float4 w = w4[lane + k * 32];
        acc = fmaf(v.x, w.x, acc);
        acc = fmaf(v.y, w.y, acc);
        acc = fmaf(v.z, w.z, acc);
        acc = fmaf(v.w, w.w, acc);
    }

    #pragma unroll
    for (int off = 16; off > 0; off >>= 1)
        acc += __shfl_xor_sync(0xFFFFFFFFu, acc, off);

    if (lane == 0) out[gwarp] = acc + bptr[0];
}

// ---------------------------------------------------------------------------
extern "C" void kernel_launch(void* const* d_in, const int* in_sizes, int n_in,
                              void* d_out, int out_size)
{
    const float* x   = (const float*)d_in[0];   // [32768, 3, 16, 16]
    const float* lhs = (const float*)d_in[1];   // [2, 16, 8]
    const float* rhs = (const float*)d_in[2];   // [2, 8, 16]
    const float* W   = (const float*)d_in[3];   // [1, 3072]
    const float* b   = (const float*)d_in[4];   // [1]
    float* out       = (float*)d_out;           // [32768]

    fold_weff_kernel<<<D, 256>>>(lhs, rhs, W);

    // 32768 rows, 1 warp each, 4 warps per block -> 8192 blocks
    gemv_kernel<<<BATCH / 4, 128>>>((const float4*)x, b, out);
}

// round 3
// speedup vs baseline: 1.1267x; 1.1267x over previous
#include <cuda_runtime.h>
#include <cuda_bf16.h>

// Problem constants
#define BATCH   32768
#define D       768          // 3*16*16 compressed features per sample
#define D4      192          // D/4

__device__ float g_weff[D];

// ---------------------------------------------------------------------------
// Kernel 1: fold lhs/rhs/W into W_eff[768].
// One block per output element o = ch*256 + (r*8+p)*16 + (c*8+q).
// ---------------------------------------------------------------------------
__global__ void fold_weff_kernel(const float* __restrict__ lhs,   // [2,16,8]
                                 const float* __restrict__ rhs,   // [2,8,16]
                                 const float* __restrict__ W)     // [3072]
{
    const int o   = blockIdx.x;          // 0..767
    const int ch  = o >> 8;
    const int rem = o & 255;
    const int rr  = rem >> 4;
    const int cc  = rem & 15;
    const int r   = rr >> 3;
    const int p   = rr & 7;
    const int c   = cc >> 3;
    const int q   = cc & 7;

    const int t = threadIdx.x;           // 0..255
    const int P = t >> 4;
    const int Q = t & 15;

    float term = lhs[r * 128 + P * 8 + p]
               * rhs[c * 128 + q * 16 + Q]
               * W[ch * 1024 + (r * 16 + P) * 32 + (c * 16 + Q)];

    #pragma unroll
    for (int off = 16; off > 0; off >>= 1)
        term += __shfl_xor_sync(0xFFFFFFFFu, term, off);

    __shared__ float warp_sums[8];
    const int lane = t & 31;
    const int wid  = t >> 5;
    if (lane == 0) warp_sums[wid] = term;
    __syncthreads();

    if (t == 0) {
        float s = 0.f;
        #pragma unroll
        for (int w = 0; w < 8; w++) s += warp_sums[w];
        g_weff[o] = s;
    }
}

// ---------------------------------------------------------------------------
// Kernel 2: out[n] = dot(x[n,:], W_eff) + b.
// 256 threads = 8 warps; each warp handles 2 rows -> 16 rows per block.
// All 12 x float4 loads issued up front (MLP=12/warp), weights from smem.
// x is read exactly once -> streaming hint (__ldcs).
// ---------------------------------------------------------------------------
__global__ __launch_bounds__(256)
void gemv_kernel(const float4* __restrict__ x,    // [BATCH * D4]
                 const float*  __restrict__ bptr, // [1]
                 float*        __restrict__ out)  // [BATCH]
{
    __shared__ float4 sw[D4];

    const int t = threadIdx.x;
    if (t < D4) sw[t] = reinterpret_cast<const float4*>(g_weff)[t];
    __syncthreads();

    const int warp = t >> 5;
    const int lane = t & 31;
    const int row0 = (blockIdx.x * 8 + warp) * 2;

    const float4* __restrict__ xr0 = x + (size_t)row0 * D4;
    const float4* __restrict__ xr1 = xr0 + D4;

    // Issue all 12 global loads before any FMA: maximize loads in flight.
    float4 v0[6], v1[6];
    #pragma unroll
    for (int k = 0; k < 6; k++) v0[k] = __ldcs(&xr0[lane + k * 32]);
    #pragma unroll
    for (int k = 0; k < 6; k++) v1[k] = __ldcs(&xr1[lane + k * 32]);

    float a0 = 0.f, a1 = 0.f;
    #pragma unroll
    for (int k = 0; k < 6; k++) {
        const float4 w = sw[lane + k * 32];
        a0 = fmaf(v0[k].x, w.x, a0);
        a0 = fmaf(v0[k].y, w.y, a0);
        a0 = fmaf(v0[k].z, w.z, a0);
        a0 = fmaf(v0[k].w, w.w, a0);
        a1 = fmaf(v1[k].x, w.x, a1);
        a1 = fmaf(v1[k].y, w.y, a1);
        a1 = fmaf(v1[k].z, w.z, a1);
        a1 = fmaf(v1[k].w, w.w, a1);
    }

    #pragma unroll
    for (int off = 16; off > 0; off >>= 1) {
        a0 += __shfl_xor_sync(0xFFFFFFFFu, a0, off);
        a1 += __shfl_xor_sync(0xFFFFFFFFu, a1, off);
    }

    if (lane == 0) {
        const float bb = bptr[0];
        out[row0]     = a0 + bb;
        out[row0 + 1] = a1 + bb;
    }
}

// ---------------------------------------------------------------------------
extern "C" void kernel_launch(void* const* d_in, const int* in_sizes, int n_in,
                              void* d_out, int out_size)
{
    const float* x   = (const float*)d_in[0];   // [32768, 3, 16, 16]
    const float* lhs = (const float*)d_in[1];   // [2, 16, 8]
    const float* rhs = (const float*)d_in[2];   // [2, 8, 16]
    const float* W   = (const float*)d_in[3];   // [1, 3072]
    const float* b   = (const float*)d_in[4];   // [1]
    float* out       = (float*)d_out;           // [32768]

    fold_weff_kernel<<<D, 256>>>(lhs, rhs, W);

    // 16 rows per block -> 2048 blocks
    gemv_kernel<<<BATCH / 16, 256>>>((const float4*)x, b, out);
}